// round 5
// baseline (speedup 1.0000x reference)
#include <cuda_runtime.h>
#include <cuda_bf16.h>
#include <cstdint>

#define HDIM 4096
#define EXP  64
#define NCH  (HDIM / 16)     // 256 k16 chunks
#define MARG 1e-4f
#define BANDCAP 256
#define FIXCAP  1024

// ---------------------------------------------------------------------------
// Device globals (no dynamic allocation allowed)
// ---------------------------------------------------------------------------
__device__ float    g_thresh[EXP];
__device__ unsigned g_hist0[EXP * 64];
__device__ uint4    g_Ws[3][32768];   // 3 bf16 splits of W^T: [64 experts][4096 k]
__device__ unsigned long long g_claim[32768];
__device__ int      g_band_n[EXP];
__device__ int      g_above[EXP];
__device__ int      g_band_t[EXP][BANDCAP];
__device__ float    g_band_v[EXP][BANDCAP];
__device__ int      g_fix_n;
__device__ int4     g_fix[FIXCAP];

// 32B-row swizzle: XOR bit4 with bit7 (conflict-free ldmatrix/STS on 32B rows)
__device__ __forceinline__ unsigned SWZ32(unsigned o) { return o ^ ((o >> 3) & 0x10u); }

__device__ __forceinline__ unsigned sortable(float f) {
    unsigned u = __float_as_uint(f);
    return u ^ ((u & 0x80000000u) ? 0xFFFFFFFFu : 0x80000000u);
}

__device__ __forceinline__ void ldsm_x4(unsigned& r0, unsigned& r1, unsigned& r2, unsigned& r3,
                                        uint32_t addr) {
    asm volatile("ldmatrix.sync.aligned.m8n8.x4.shared.b16 {%0,%1,%2,%3}, [%4];"
                 : "=r"(r0), "=r"(r1), "=r"(r2), "=r"(r3) : "r"(addr));
}
__device__ __forceinline__ void mma16816(float* c, const unsigned* a, unsigned b0, unsigned b1) {
    asm volatile("mma.sync.aligned.m16n8k16.row.col.f32.bf16.bf16.f32 "
                 "{%0,%1,%2,%3}, {%4,%5,%6,%7}, {%8,%9}, {%0,%1,%2,%3};"
                 : "+f"(c[0]), "+f"(c[1]), "+f"(c[2]), "+f"(c[3])
                 : "r"(a[0]), "r"(a[1]), "r"(a[2]), "r"(a[3]), "r"(b0), "r"(b1));
}
__device__ __forceinline__ uint32_t smem_u32(const void* p) {
    uint32_t a;
    asm("{ .reg .u64 t; cvta.to.shared.u64 t, %1; cvt.u32.u64 %0, t; }" : "=r"(a) : "l"(p));
    return a;
}
// fp32 pair -> 3 packed bf16x2 splits (lo = first element)
__device__ __forceinline__ void split3(float a0, float a1, unsigned& u1, unsigned& u2, unsigned& u3) {
    union { __nv_bfloat162 b; unsigned u; } cv;
    cv.b = __floats2bfloat162_rn(a0, a1); u1 = cv.u;
    float f0 = __uint_as_float(u1 << 16);
    float f1 = __uint_as_float(u1 & 0xFFFF0000u);
    float r0 = a0 - f0, r1 = a1 - f1;
    cv.b = __floats2bfloat162_rn(r0, r1); u2 = cv.u;
    float g0 = __uint_as_float(u2 << 16);
    float g1 = __uint_as_float(u2 & 0xFFFF0000u);
    cv.b = __floats2bfloat162_rn(r0 - g0, r1 - g1); u3 = cv.u;
}

// EXACT logit: sequential k-ascending fp32 FMA chain (bit-identical to the
// R1 kernel whose selection passed). Do not reorder.
__device__ __noinline__ float exact_dot(const float* __restrict__ x,
                                        const float* __restrict__ W,
                                        int t, int e) {
    const float* xp = x + (size_t)t * HDIM;
    const float* wp = W + e;
    float acc = 0.f;
#pragma unroll 8
    for (int k = 0; k < HDIM; ++k)
        acc = fmaf(xp[k], wp[(size_t)k * EXP], acc);
    return acc;
}

// strict ordering: (value desc, index asc)
__device__ __forceinline__ bool better(float v1, int i1, float v2, int i2) {
    return (v1 > v2) || (v1 == v2 && i1 < i2);
}

// ---------------------------------------------------------------------------
// Kernel 0: pre-split W[4096,64] into 3 bf16 transposed matrices [64][4096]
// ---------------------------------------------------------------------------
__global__ __launch_bounds__(256) void wsplit_kernel(const float* __restrict__ W) {
    int idx = blockIdx.x * 256 + threadIdx.x;
    if (idx >= HDIM * EXP) return;
    int k = idx >> 6, e = idx & 63;
    float v = W[idx];
    __nv_bfloat16 h1 = __float2bfloat16_rn(v);
    float f1 = __uint_as_float(((unsigned)__bfloat16_as_ushort(h1)) << 16);
    float r1 = v - f1;
    __nv_bfloat16 h2 = __float2bfloat16_rn(r1);
    float f2 = __uint_as_float(((unsigned)__bfloat16_as_ushort(h2)) << 16);
    __nv_bfloat16 h3 = __float2bfloat16_rn(r1 - f2);
    size_t o = (size_t)e * HDIM + k;
    ((__nv_bfloat16*)g_Ws[0])[o] = h1;
    ((__nv_bfloat16*)g_Ws[1])[o] = h2;
    ((__nv_bfloat16*)g_Ws[2])[o] = h3;
}

// ---------------------------------------------------------------------------
// Kernel 1: logits = x @ W via 6-product bf16 split on mma.sync (HMMA)
// ---------------------------------------------------------------------------
__global__ __launch_bounds__(256, 2) void gemm_kernel(const float* __restrict__ x,
                                                      float* __restrict__ logits) {
    __shared__ char As[2][3][128 * 32];
    __shared__ char Bs[2][3][64 * 32];

    const int tid  = threadIdx.x;
    const int wid  = tid >> 5;
    const int lane = tid & 31;
    const int row0 = blockIdx.x * 128;

    const int xr = tid >> 1;
    const int xg = tid & 1;
    const float* xptr = x + (size_t)(row0 + xr) * HDIM + xg * 8;
    const unsigned a_st = SWZ32((unsigned)(xr * 32 + xg * 16));

    const int bs = tid >> 6;
    const int bn = tid & 63;
    const bool bact = (tid < 192);
    const unsigned b_st0 = SWZ32((unsigned)(bn * 32));
    const unsigned b_st1 = SWZ32((unsigned)(bn * 32 + 16));

    const unsigned aoff = SWZ32((unsigned)((wid * 16 + (lane & 15)) * 32 + (lane >> 4) * 16));
    const unsigned boff = SWZ32((unsigned)((((lane & 7) + ((lane >> 4) << 3)) * 32) + ((lane >> 3) & 1) * 16));

    float acc[4][8];
#pragma unroll
    for (int nb = 0; nb < 4; ++nb)
#pragma unroll
        for (int j = 0; j < 8; ++j) acc[nb][j] = 0.f;

    float4 xa0 = *(const float4*)xptr;
    float4 xa1 = *(const float4*)(xptr + 4);
    uint4 bw0, bw1;
    if (bact) { bw0 = g_Ws[bs][bn * 512]; bw1 = g_Ws[bs][bn * 512 + 1]; }

    for (int c = 0; c < NCH; ++c) {
        const int buf = c & 1;
        {
            unsigned u1a, u2a, u3a, u1b, u2b, u3b, u1c, u2c, u3c, u1d, u2d, u3d;
            split3(xa0.x, xa0.y, u1a, u2a, u3a);
            split3(xa0.z, xa0.w, u1b, u2b, u3b);
            split3(xa1.x, xa1.y, u1c, u2c, u3c);
            split3(xa1.z, xa1.w, u1d, u2d, u3d);
            *(uint4*)(As[buf][0] + a_st) = make_uint4(u1a, u1b, u1c, u1d);
            *(uint4*)(As[buf][1] + a_st) = make_uint4(u2a, u2b, u2c, u2d);
            *(uint4*)(As[buf][2] + a_st) = make_uint4(u3a, u3b, u3c, u3d);
            if (bact) {
                *(uint4*)(Bs[buf][bs] + b_st0) = bw0;
                *(uint4*)(Bs[buf][bs] + b_st1) = bw1;
            }
        }
        __syncthreads();
        if (c + 1 < NCH) {
            xa0 = *(const float4*)(xptr + (c + 1) * 16);
            xa1 = *(const float4*)(xptr + (c + 1) * 16 + 4);
            if (bact) {
                bw0 = g_Ws[bs][bn * 512 + (c + 1) * 2];
                bw1 = g_Ws[bs][bn * 512 + (c + 1) * 2 + 1];
            }
        }
        unsigned a[3][4];
#pragma unroll
        for (int s = 0; s < 3; ++s)
            ldsm_x4(a[s][0], a[s][1], a[s][2], a[s][3], smem_u32(As[buf][s]) + aoff);
#pragma unroll
        for (int sb = 0; sb < 3; ++sb) {
            unsigned b[4][4];
            const uint32_t bbase = smem_u32(Bs[buf][sb]) + boff;
#pragma unroll
            for (int nb = 0; nb < 4; ++nb)
                ldsm_x4(b[nb][0], b[nb][1], b[nb][2], b[nb][3], bbase + nb * 512);
            const int nsa = (sb == 0) ? 3 : (sb == 1) ? 2 : 1;
#pragma unroll
            for (int sa = 0; sa < 3; ++sa) {
                if (sa >= nsa) break;
#pragma unroll
                for (int nb = 0; nb < 4; ++nb) {
                    mma16816(&acc[nb][0], a[sa], b[nb][0], b[nb][1]);
                    mma16816(&acc[nb][4], a[sa], b[nb][2], b[nb][3]);
                }
            }
        }
    }

    const int r0 = row0 + wid * 16 + (lane >> 2);
    const int r1 = r0 + 8;
    const int cb = (lane & 3) * 2;
#pragma unroll
    for (int nb = 0; nb < 4; ++nb) {
        float* p0 = logits + (size_t)r0 * EXP + nb * 16 + cb;
        float* p1 = logits + (size_t)r1 * EXP + nb * 16 + cb;
        *(float2*)p0       = make_float2(acc[nb][0], acc[nb][1]);
        *(float2*)p1       = make_float2(acc[nb][2], acc[nb][3]);
        *(float2*)(p0 + 8) = make_float2(acc[nb][4], acc[nb][5]);
        *(float2*)(p1 + 8) = make_float2(acc[nb][6], acc[nb][7]);
    }
}

// ---------------------------------------------------------------------------
// Kernel 2: fused row-major top-6-bit histograms for all 64 experts
// ---------------------------------------------------------------------------
__global__ __launch_bounds__(256) void hist0_kernel(const float* __restrict__ logits) {
    __shared__ unsigned h[EXP * 64];
    for (int i = threadIdx.x; i < EXP * 64; i += 256) h[i] = 0;
    __syncthreads();
    const int row0 = blockIdx.x * 128;
#pragma unroll
    for (int j = 0; j < 8; ++j) {
        int u = threadIdx.x + j * 256;
        int r = u >> 4, cg = u & 15;
        float4 v = *(const float4*)(logits + (size_t)(row0 + r) * EXP + cg * 4);
        float vv[4] = {v.x, v.y, v.z, v.w};
#pragma unroll
        for (int m = 0; m < 4; ++m)
            atomicAdd(&h[(cg * 4 + m) * 64 + (sortable(vv[m]) >> 26)], 1u);
    }
    __syncthreads();
    for (int i = threadIdx.x; i < EXP * 64; i += 256) {
        unsigned c = h[i];
        if (c) atomicAdd(&g_hist0[i], c);
    }
}

// ---------------------------------------------------------------------------
// Kernel 3: per-expert k-th largest of FAST logits (gather + local radix)
// ---------------------------------------------------------------------------
#define CAP 5632
__global__ __launch_bounds__(256) void select2_kernel(const float* __restrict__ logits,
                                                      int N, int k) {
    __shared__ unsigned cand[2][CAP];
    __shared__ unsigned hist[256];
    __shared__ unsigned s_cnt, s_bv, s_remk, s_prefix, s_n2;
    const int e   = blockIdx.x;
    const int tid = threadIdx.x;

    if (tid == 0) {
        unsigned remk = (unsigned)k, cum = 0;
        int b = 63;
        for (; b > 0; --b) { unsigned hh = g_hist0[e * 64 + b]; if (cum + hh >= remk) break; cum += hh; }
        s_bv = (unsigned)b; s_remk = remk - cum; s_cnt = 0; s_prefix = 0;
    }
    __syncthreads();
    const unsigned b0 = s_bv;
    const unsigned bucket_n = g_hist0[e * 64 + b0];
    const int SH[4] = {18, 10, 2, 0};
    const unsigned MK[4] = {255, 255, 255, 3};

    if (bucket_n <= CAP) {
        for (int i = tid; i < N; i += 256) {
            unsigned u = sortable(logits[(size_t)i * EXP + e]);
            if ((u >> 26) == b0) { unsigned p = atomicAdd(&s_cnt, 1u); cand[0][p] = u; }
        }
        __syncthreads();
        int n = (int)s_cnt, cur = 0;
        for (int p = 0; p < 4; ++p) {
            const int sh = SH[p]; const unsigned mk = MK[p];
            hist[tid] = 0;
            __syncthreads();
            for (int j = tid; j < n; j += 256) atomicAdd(&hist[(cand[cur][j] >> sh) & mk], 1u);
            __syncthreads();
            if (tid == 0) {
                unsigned remk = s_remk, cum = 0;
                int b = (int)mk;
                for (; b > 0; --b) { unsigned hh = hist[b]; if (cum + hh >= remk) break; cum += hh; }
                s_bv = (unsigned)b; s_remk = remk - cum; s_prefix |= ((unsigned)b) << sh; s_n2 = 0;
            }
            __syncthreads();
            if (p < 3) {
                unsigned bv = s_bv;
                for (int j = tid; j < n; j += 256) {
                    unsigned key = cand[cur][j];
                    if (((key >> sh) & mk) == bv) { unsigned q = atomicAdd(&s_n2, 1u); cand[1 - cur][q] = key; }
                }
                __syncthreads();
                n = (int)s_n2; cur ^= 1;
            }
        }
        if (tid == 0) {
            unsigned key = (b0 << 26) | s_prefix;
            unsigned bits = (key & 0x80000000u) ? (key ^ 0x80000000u) : ~key;
            g_thresh[e] = __uint_as_float(bits);
        }
    } else {
        unsigned pmask = 0xFC000000u;
        if (tid == 0) s_prefix = b0 << 26;
        __syncthreads();
        for (int p = 0; p < 4; ++p) {
            const int sh = SH[p]; const unsigned mk = MK[p];
            hist[tid] = 0;
            __syncthreads();
            const unsigned pre = s_prefix;
            for (int i = tid; i < N; i += 256) {
                unsigned u = sortable(logits[(size_t)i * EXP + e]);
                if ((u & pmask) == pre) atomicAdd(&hist[(u >> sh) & mk], 1u);
            }
            __syncthreads();
            if (tid == 0) {
                unsigned remk = s_remk, cum = 0;
                int b = (int)mk;
                for (; b > 0; --b) { unsigned hh = hist[b]; if (cum + hh >= remk) break; cum += hh; }
                s_prefix = pre | (((unsigned)b) << sh); s_remk = remk - cum;
            }
            pmask |= mk << sh;
            __syncthreads();
        }
        if (tid == 0) {
            unsigned key = s_prefix;
            unsigned bits = (key & 0x80000000u) ? (key ^ 0x80000000u) : ~key;
            g_thresh[e] = __uint_as_float(bits);
        }
    }
}

// ---------------------------------------------------------------------------
// Kernel 4: band classification + exact recompute of band candidates
// ---------------------------------------------------------------------------
__global__ __launch_bounds__(256) void band_kernel(const float* __restrict__ logits,
                                                   const float* __restrict__ x,
                                                   const float* __restrict__ W) {
    __shared__ float th[EXP];
    __shared__ int cnt[EXP];
    if (threadIdx.x < EXP) { th[threadIdx.x] = g_thresh[threadIdx.x]; cnt[threadIdx.x] = 0; }
    __syncthreads();
    int u = blockIdx.x * 256 + threadIdx.x;   // one float4 (4 experts) per thread
    int t = u >> 4, eg = (u & 15) * 4;
    float4 v = *(const float4*)(logits + (size_t)t * EXP + eg);
    float vv[4] = {v.x, v.y, v.z, v.w};
#pragma unroll
    for (int m = 0; m < 4; ++m) {
        int e = eg + m;
        float T = th[e];
        float l = vv[m];
        if (l > T + MARG) {
            atomicAdd(&cnt[e], 1);
        } else if (l > T - MARG) {
            int idx = atomicAdd(&g_band_n[e], 1);
            if (idx < BANDCAP) {
                g_band_t[e][idx] = t;
                g_band_v[e][idx] = exact_dot(x, W, t, e);
            }
        }
    }
    __syncthreads();
    if (threadIdx.x < EXP && cnt[threadIdx.x])
        atomicAdd(&g_above[threadIdx.x], cnt[threadIdx.x]);
}

// ---------------------------------------------------------------------------
// Kernel 5: per-expert resolve — claim top (k - above) band tokens by exact v
// ---------------------------------------------------------------------------
__global__ __launch_bounds__(256) void resolve_kernel(int k) {
    __shared__ float sv[BANDCAP];
    __shared__ int   st[BANDCAP];
    const int e = blockIdx.x;
    int n = g_band_n[e];
    if (n > BANDCAP) n = BANDCAP;
    int need = k - g_above[e];
    if (need > n) need = n;
    for (int i = threadIdx.x; i < n; i += 256) { sv[i] = g_band_v[e][i]; st[i] = g_band_t[e][i]; }
    __syncthreads();
    for (int i = threadIdx.x; i < n; i += 256) {
        float v = sv[i]; int t = st[i];
        int rank = 0;
        for (int j = 0; j < n; ++j)
            if (better(sv[j], st[j], v, t)) ++rank;
        if (rank < need)
            atomicOr(&g_claim[t], 1ull << e);
    }
}

// ---------------------------------------------------------------------------
// Kernel 6: conflict resolution + fallback argmax, with top-2 margin check.
// One warp per token.
// ---------------------------------------------------------------------------
__device__ __forceinline__ void merge2(float& bv, int& bi, float& sv, int& si,
                                       float ov, int oi, float o2v, int o2i) {
    if (better(ov, oi, bv, bi)) {
        if (better(bv, bi, o2v, o2i)) { sv = bv; si = bi; }
        else                          { sv = o2v; si = o2i; }
        bv = ov; bi = oi;
    } else if (better(ov, oi, sv, si)) {
        sv = ov; si = oi;
    }
}

__global__ __launch_bounds__(256) void assign_kernel(const float* __restrict__ logits,
                                                     float* __restrict__ out_w,
                                                     float* __restrict__ out_i,
                                                     int N) {
    const int gwarp = (int)((blockIdx.x * (size_t)blockDim.x + threadIdx.x) >> 5);
    const int lane  = threadIdx.x & 31;
    if (gwarp >= N) return;

    const float NEG_INF = __int_as_float(0xff800000);
    const int e0 = lane * 2, e1 = lane * 2 + 1;
    float2 v = *(const float2*)(logits + (size_t)gwarp * EXP + e0);
    float t0 = g_thresh[e0], t1 = g_thresh[e1];
    unsigned long long mask = g_claim[gwarp];

    bool c0 = (v.x > t0 + MARG) || ((mask >> e0) & 1ull);
    bool c1 = (v.y > t1 + MARG) || ((mask >> e1) & 1ull);

    // claimed best/second
    float cbv = NEG_INF, csv = NEG_INF; int cbi = 1000, csi = 1000;
    if (c0) { cbv = v.x; cbi = e0; }
    if (c1) merge2(cbv, cbi, csv, csi, v.y, e1, NEG_INF, 1000);
    // fallback best/second
    float fbv, fsv; int fbi, fsi;
    if (better(v.x, e0, v.y, e1)) { fbv = v.x; fbi = e0; fsv = v.y; fsi = e1; }
    else                          { fbv = v.y; fbi = e1; fsv = v.x; fsi = e0; }

#pragma unroll
    for (int off = 16; off; off >>= 1) {
        float ob = __shfl_xor_sync(0xFFFFFFFFu, cbv, off);
        int   obi = __shfl_xor_sync(0xFFFFFFFFu, cbi, off);
        float os = __shfl_xor_sync(0xFFFFFFFFu, csv, off);
        int   osi = __shfl_xor_sync(0xFFFFFFFFu, csi, off);
        merge2(cbv, cbi, csv, csi, ob, obi, os, osi);
        float fb = __shfl_xor_sync(0xFFFFFFFFu, fbv, off);
        int   fbio = __shfl_xor_sync(0xFFFFFFFFu, fbi, off);
        float fso = __shfl_xor_sync(0xFFFFFFFFu, fsv, off);
        int   fsio = __shfl_xor_sync(0xFFFFFFFFu, fsi, off);
        merge2(fbv, fbi, fsv, fsi, fb, fbio, fso, fsio);
    }

    if (lane == 0) {
        float w; int e;
        bool assigned = (cbi < EXP);
        if (assigned) {
            w = cbv; e = cbi;
            if (csi < EXP && cbv - csv < MARG) {
                int fi2 = atomicAdd(&g_fix_n, 1);
                if (fi2 < FIXCAP) g_fix[fi2] = make_int4(gwarp, cbi, csi, 0);
            }
        } else {
            w = fbv; e = fbi;
            if (fbv - fsv < MARG) {
                int fi2 = atomicAdd(&g_fix_n, 1);
                if (fi2 < FIXCAP) g_fix[fi2] = make_int4(gwarp, fbi, fsi, 1);
            }
        }
        out_w[gwarp] = w;
        out_i[gwarp] = (float)e;
    }
}

// ---------------------------------------------------------------------------
// Kernel 7: exact fixup of ambiguous winners
// ---------------------------------------------------------------------------
__global__ __launch_bounds__(256) void fix_kernel(const float* __restrict__ x,
                                                  const float* __restrict__ W,
                                                  float* __restrict__ out_w,
                                                  float* __restrict__ out_i) {
    int idx = blockIdx.x * 256 + threadIdx.x;
    int n = g_fix_n;
    if (n > FIXCAP) n = FIXCAP;
    if (idx >= n) return;
    int4 f = g_fix[idx];
    int t = f.x, ea = f.y, eb = f.z;
    float va = exact_dot(x, W, t, ea);
    float vb = exact_dot(x, W, t, eb);
    int win; float wv;
    if (better(vb, eb, va, ea)) { win = eb; wv = vb; }
    else                        { win = ea; wv = va; }
    out_w[t] = wv;
    out_i[t] = (float)win;
}

// ---------------------------------------------------------------------------
// Output layout: [0,N) weights | [N,2N) indices (float) | [2N, 2N+N*E) logits
// ---------------------------------------------------------------------------
extern "C" void kernel_launch(void* const* d_in, const int* in_sizes, int n_in,
                              void* d_out, int out_size) {
    const float* x = (const float*)d_in[0];
    const float* W = (const float*)d_in[1];
    const int N = in_sizes[0] / HDIM;   // 32768

    float* out    = (float*)d_out;
    float* out_w  = out;
    float* out_i  = out + N;
    float* logits = out + 2 * (size_t)N;

    int k = N / EXP;
    if (k < 1) k = 1;
    if (k > N) k = N;

    void* p;
    cudaGetSymbolAddress(&p, g_hist0);  cudaMemsetAsync(p, 0, EXP * 64 * sizeof(unsigned));
    cudaGetSymbolAddress(&p, g_claim);  cudaMemsetAsync(p, 0, (size_t)N * 8);
    cudaGetSymbolAddress(&p, g_band_n); cudaMemsetAsync(p, 0, EXP * sizeof(int));
    cudaGetSymbolAddress(&p, g_above);  cudaMemsetAsync(p, 0, EXP * sizeof(int));
    cudaGetSymbolAddress(&p, g_fix_n);  cudaMemsetAsync(p, 0, sizeof(int));

    wsplit_kernel<<<(HDIM * EXP + 255) / 256, 256>>>(W);
    gemm_kernel<<<N / 128, 256>>>(x, logits);
    hist0_kernel<<<N / 128, 256>>>(logits);
    select2_kernel<<<EXP, 256>>>(logits, N, k);
    band_kernel<<<(N * 16) / 256, 256>>>(logits, x, W);
    resolve_kernel<<<EXP, 256>>>(k);
    assign_kernel<<<(int)(((size_t)N * 32 + 255) / 256), 256>>>(logits, out_w, out_i, N);
    fix_kernel<<<(FIXCAP + 255) / 256, 256>>>(x, W, out_w, out_i);
}

// round 9
// speedup vs baseline: 1.4769x; 1.4769x over previous
#include <cuda_runtime.h>
#include <cstdint>

#define HDIM 4096
#define EXP  64
#define BM   128
#define BK   16
#define NCH  (HDIM / BK)   // 256
#define GCAP 8192

typedef unsigned long long ull;

// ---------------------------------------------------------------------------
// Device globals
// ---------------------------------------------------------------------------
__device__ float    g_thresh[EXP];
__device__ unsigned g_hist0[EXP * 64];
__device__ unsigned g_b0[EXP];
__device__ unsigned g_remk[EXP];
__device__ int      g_cand_n[EXP];
__device__ unsigned g_cand[EXP][GCAP];
__device__ unsigned g_cand2[EXP][GCAP];

__device__ __forceinline__ unsigned sortable(float f) {
    unsigned u = __float_as_uint(f);
    return u ^ ((u & 0x80000000u) ? 0xFFFFFFFFu : 0x80000000u);
}

// ---------------------------------------------------------------------------
// Kernel 1: logits[N,64] = x[N,4096] @ W[4096,64], exact fp32 (k-ascending
// FFMA2 chains — same arithmetic order as the R1 kernel that passed).
// ---------------------------------------------------------------------------
__global__ __launch_bounds__(256, 2) void gemm_kernel(const float* __restrict__ x,
                                                      const float* __restrict__ W,
                                                      float* __restrict__ logits) {
    __shared__ __align__(16) float  xs[2][BK][132];   // [k][row], padded row 528B
    __shared__ __align__(16) float2 ws[2][BK][66];    // [k][col] duplicated (w,w)

    const int tid  = threadIdx.x;
    const int row0 = blockIdx.x * BM;
    const int cg   = tid & 15;        // cols cg*4 .. +3
    const int rg   = tid >> 4;        // rows rg*8 .. +7

    // staging maps
    const int xr0  = tid >> 2;        // x float4 #0: row
    const int xkq  = tid & 3;         // k sub-quad (cols xkq*4..+3 of chunk)
    const int xr1  = xr0 + 64;        // x float4 #1: row
    const int wk   = tid >> 4;        // W row within chunk
    const int wc   = (tid & 15) * 4;  // W col quad

    const float* xp0 = x + (size_t)(row0 + xr0) * HDIM + xkq * 4;
    const float* xp1 = x + (size_t)(row0 + xr1) * HDIM + xkq * 4;
    const float* wp  = W + (size_t)wk * EXP + wc;

    ull acc[4][4];   // [col j][row-pair i]; lanes = (row rg*8+2i, +1)
#pragma unroll
    for (int j = 0; j < 4; ++j)
#pragma unroll
        for (int i = 0; i < 4; ++i) acc[j][i] = 0ULL;

    // prefetch chunk 0
    float4 vx0 = *(const float4*)xp0;
    float4 vx1 = *(const float4*)xp1;
    float4 vw  = *(const float4*)wp;

    // stage chunk 0 into buf 0
    {
        float a0[4] = {vx0.x, vx0.y, vx0.z, vx0.w};
        float a1[4] = {vx1.x, vx1.y, vx1.z, vx1.w};
        float b[4]  = {vw.x, vw.y, vw.z, vw.w};
#pragma unroll
        for (int j = 0; j < 4; ++j) {
            xs[0][xkq * 4 + j][xr0] = a0[j];
            xs[0][xkq * 4 + j][xr1] = a1[j];
            ws[0][wk][wc + j] = make_float2(b[j], b[j]);
        }
    }
    __syncthreads();

    for (int c = 0; c < NCH; ++c) {
        const int buf = c & 1;
        // issue next-chunk LDGs early (latency covered by compute)
        if (c + 1 < NCH) {
            vx0 = *(const float4*)(xp0 + (c + 1) * BK);
            vx1 = *(const float4*)(xp1 + (c + 1) * BK);
            vw  = *(const float4*)(wp + (size_t)(c + 1) * BK * EXP);
        }
        // compute 16 k's
#pragma unroll
        for (int k = 0; k < BK; ++k) {
            const float*  ar = &xs[buf][k][rg * 8];
            const float2* br = &ws[buf][k][cg * 4];
            ull a2[4], b2[4];
#pragma unroll
            for (int i = 0; i < 4; ++i) a2[i] = *(const ull*)(ar + 2 * i);
#pragma unroll
            for (int j = 0; j < 4; ++j) b2[j] = *(const ull*)(br + j);
#pragma unroll
            for (int j = 0; j < 4; ++j)
#pragma unroll
                for (int i = 0; i < 4; ++i)
                    asm("fma.rn.f32x2 %0, %1, %2, %0;"
                        : "+l"(acc[j][i]) : "l"(a2[i]), "l"(b2[j]));
        }
        // stage next chunk into the other buffer
        if (c + 1 < NCH) {
            float a0[4] = {vx0.x, vx0.y, vx0.z, vx0.w};
            float a1[4] = {vx1.x, vx1.y, vx1.z, vx1.w};
            float b[4]  = {vw.x, vw.y, vw.z, vw.w};
            const int nb = buf ^ 1;
#pragma unroll
            for (int j = 0; j < 4; ++j) {
                xs[nb][xkq * 4 + j][xr0] = a0[j];
                xs[nb][xkq * 4 + j][xr1] = a1[j];
                ws[nb][wk][wc + j] = make_float2(b[j], b[j]);
            }
        }
        __syncthreads();
    }

    // writeback: 8 rows x 4 cols, float4 per row
#pragma unroll
    for (int i = 0; i < 4; ++i) {
        float lo[4], hi[4];
#pragma unroll
        for (int j = 0; j < 4; ++j) {
            lo[j] = __uint_as_float((unsigned)(acc[j][i] & 0xFFFFFFFFULL));
            hi[j] = __uint_as_float((unsigned)(acc[j][i] >> 32));
        }
        int r = row0 + rg * 8 + i * 2;
        *(float4*)(logits + (size_t)r * EXP + cg * 4) =
            make_float4(lo[0], lo[1], lo[2], lo[3]);
        *(float4*)(logits + (size_t)(r + 1) * EXP + cg * 4) =
            make_float4(hi[0], hi[1], hi[2], hi[3]);
    }
}

// ---------------------------------------------------------------------------
// Kernel 2: fused row-major top-6-bit histograms for all 64 experts
// ---------------------------------------------------------------------------
__global__ __launch_bounds__(256) void hist0_kernel(const float* __restrict__ logits) {
    __shared__ unsigned h[EXP * 64];
    for (int i = threadIdx.x; i < EXP * 64; i += 256) h[i] = 0;
    __syncthreads();
    const int row0 = blockIdx.x * 128;
#pragma unroll
    for (int j = 0; j < 8; ++j) {
        int u = threadIdx.x + j * 256;
        int r = u >> 4, cgq = u & 15;
        float4 v = *(const float4*)(logits + (size_t)(row0 + r) * EXP + cgq * 4);
        float vv[4] = {v.x, v.y, v.z, v.w};
#pragma unroll
        for (int m = 0; m < 4; ++m)
            atomicAdd(&h[(cgq * 4 + m) * 64 + (sortable(vv[m]) >> 26)], 1u);
    }
    __syncthreads();
    for (int i = threadIdx.x; i < EXP * 64; i += 256) {
        unsigned c = h[i];
        if (c) atomicAdd(&g_hist0[i], c);
    }
}

// ---------------------------------------------------------------------------
// Kernel 3: pick top bucket + residual k per expert
// ---------------------------------------------------------------------------
__global__ void bucket_kernel(int k) {
    int e = threadIdx.x;   // 64 threads
    unsigned remk = (unsigned)k, cum = 0;
    int b = 63;
    for (; b > 0; --b) {
        unsigned h = g_hist0[e * 64 + b];
        if (cum + h >= remk) break;
        cum += h;
    }
    g_b0[e]   = (unsigned)b;
    g_remk[e] = remk - cum;
}

// ---------------------------------------------------------------------------
// Kernel 4: row-major gather of bucket candidates into per-expert lists
// ---------------------------------------------------------------------------
__global__ __launch_bounds__(256) void gather_kernel(const float* __restrict__ logits) {
    __shared__ unsigned sb0[EXP];
    if (threadIdx.x < EXP) sb0[threadIdx.x] = g_b0[threadIdx.x];
    __syncthreads();
    const int t = blockIdx.x * 256 + threadIdx.x;   // token row
    const float4* row = (const float4*)(logits + (size_t)t * EXP);
#pragma unroll
    for (int q = 0; q < 16; ++q) {
        float4 v = row[q];
        float vv[4] = {v.x, v.y, v.z, v.w};
#pragma unroll
        for (int m = 0; m < 4; ++m) {
            int e = q * 4 + m;
            unsigned u = sortable(vv[m]);
            if ((u >> 26) == sb0[e]) {
                int i = atomicAdd(&g_cand_n[e], 1);
                if (i < GCAP) g_cand[e][i] = u;
            }
        }
    }
}

// ---------------------------------------------------------------------------
// Kernel 5: per-expert k-th largest. Local radix on gathered candidates;
// full-column scanning fallback if the bucket overflowed GCAP.
// ---------------------------------------------------------------------------
__global__ __launch_bounds__(256) void selectf_kernel(const float* __restrict__ logits,
                                                      int N) {
    __shared__ unsigned hist[256];
    __shared__ unsigned s_bv, s_remk, s_prefix, s_n2;
    const int e   = blockIdx.x;
    const int tid = threadIdx.x;
    const unsigned b0 = g_b0[e];
    const int cn = g_cand_n[e];
    const int SH[4] = {18, 10, 2, 0};
    const unsigned MK[4] = {255, 255, 255, 3};

    if (tid == 0) { s_remk = g_remk[e]; s_prefix = 0; }
    __syncthreads();

    if (cn <= GCAP) {
        unsigned* cur = g_cand[e];
        unsigned* alt = g_cand2[e];
        int n = cn;
        for (int p = 0; p < 4; ++p) {
            const int sh = SH[p]; const unsigned mk = MK[p];
            hist[tid] = 0;
            __syncthreads();
            for (int j = tid; j < n; j += 256) atomicAdd(&hist[(cur[j] >> sh) & mk], 1u);
            __syncthreads();
            if (tid == 0) {
                unsigned remk = s_remk, cum = 0;
                int b = (int)mk;
                for (; b > 0; --b) { unsigned h = hist[b]; if (cum + h >= remk) break; cum += h; }
                s_bv = (unsigned)b; s_remk = remk - cum;
                s_prefix |= ((unsigned)b) << sh; s_n2 = 0;
            }
            __syncthreads();
            if (p < 3) {
                unsigned bv = s_bv;
                for (int j = tid; j < n; j += 256) {
                    unsigned key = cur[j];
                    if (((key >> sh) & mk) == bv) { unsigned q = atomicAdd(&s_n2, 1u); alt[q] = key; }
                }
                __syncthreads();
                n = (int)s_n2;
                unsigned* tmp = cur; cur = alt; alt = tmp;
            }
        }
        if (tid == 0) {
            unsigned key = (b0 << 26) | s_prefix;
            unsigned bits = (key & 0x80000000u) ? (key ^ 0x80000000u) : ~key;
            g_thresh[e] = __uint_as_float(bits);
        }
    } else {
        // fallback: scanning radix over the full column with growing prefix
        unsigned pmask = 0xFC000000u;
        if (tid == 0) s_prefix = b0 << 26;
        __syncthreads();
        for (int p = 0; p < 4; ++p) {
            const int sh = SH[p]; const unsigned mk = MK[p];
            hist[tid] = 0;
            __syncthreads();
            const unsigned pre = s_prefix;
            for (int i = tid; i < N; i += 256) {
                unsigned u = sortable(logits[(size_t)i * EXP + e]);
                if ((u & pmask) == pre) atomicAdd(&hist[(u >> sh) & mk], 1u);
            }
            __syncthreads();
            if (tid == 0) {
                unsigned remk = s_remk, cum = 0;
                int b = (int)mk;
                for (; b > 0; --b) { unsigned h = hist[b]; if (cum + h >= remk) break; cum += h; }
                s_prefix = pre | (((unsigned)b) << sh); s_remk = remk - cum;
            }
            pmask |= mk << sh;
            __syncthreads();
        }
        if (tid == 0) {
            unsigned key = s_prefix;
            unsigned bits = (key & 0x80000000u) ? (key ^ 0x80000000u) : ~key;
            g_thresh[e] = __uint_as_float(bits);
        }
    }
}

// ---------------------------------------------------------------------------
// Kernel 6: conflict resolution + fallback argmax. One warp per token.
// (Same semantics as the R1 kernel that passed.)
// ---------------------------------------------------------------------------
__global__ __launch_bounds__(256) void assign_kernel(const float* __restrict__ logits,
                                                     float* __restrict__ out_w,
                                                     float* __restrict__ out_i,
                                                     int N) {
    const int gwarp = (int)((blockIdx.x * (size_t)blockDim.x + threadIdx.x) >> 5);
    const int lane  = threadIdx.x & 31;
    if (gwarp >= N) return;

    const float NEG_INF = __int_as_float(0xff800000);
    float2 v = *(const float2*)(logits + (size_t)gwarp * EXP + lane * 2);
    float t0 = g_thresh[lane * 2];
    float t1 = g_thresh[lane * 2 + 1];

    float cs = NEG_INF; int ci = 127;                  // claimed best
    if (v.x >= t0)             { cs = v.x; ci = lane * 2; }
    if (v.y >= t1 && v.y > cs) { cs = v.y; ci = lane * 2 + 1; }

    float fs = v.x; int fi = lane * 2;                 // fallback argmax
    if (v.y > fs) { fs = v.y; fi = lane * 2 + 1; }

#pragma unroll
    for (int off = 16; off; off >>= 1) {
        float os = __shfl_xor_sync(0xFFFFFFFFu, cs, off);
        int   oi = __shfl_xor_sync(0xFFFFFFFFu, ci, off);
        if (os > cs || (os == cs && oi < ci)) { cs = os; ci = oi; }
        float ofs = __shfl_xor_sync(0xFFFFFFFFu, fs, off);
        int   ofi = __shfl_xor_sync(0xFFFFFFFFu, fi, off);
        if (ofs > fs || (ofs == fs && ofi < fi)) { fs = ofs; fi = ofi; }
    }

    if (lane == 0) {
        float w; int e;
        if (ci < EXP) { w = cs; e = ci; }
        else          { w = fs; e = fi; }
        out_w[gwarp] = w;
        out_i[gwarp] = (float)e;
    }
}

// ---------------------------------------------------------------------------
// Output layout: [0,N) weights | [N,2N) indices (float) | [2N, 2N+N*E) logits
// ---------------------------------------------------------------------------
extern "C" void kernel_launch(void* const* d_in, const int* in_sizes, int n_in,
                              void* d_out, int out_size) {
    const float* x = (const float*)d_in[0];
    const float* W = (const float*)d_in[1];
    const int N = in_sizes[0] / HDIM;   // 32768

    float* out    = (float*)d_out;
    float* out_w  = out;
    float* out_i  = out + N;
    float* logits = out + 2 * (size_t)N;

    int k = N / EXP;
    if (k < 1) k = 1;
    if (k > N) k = N;

    void* p;
    cudaGetSymbolAddress(&p, g_hist0);  cudaMemsetAsync(p, 0, EXP * 64 * sizeof(unsigned));
    cudaGetSymbolAddress(&p, g_cand_n); cudaMemsetAsync(p, 0, EXP * sizeof(int));

    gemm_kernel<<<N / BM, 256>>>(x, W, logits);
    hist0_kernel<<<N / 128, 256>>>(logits);
    bucket_kernel<<<1, 64>>>(k);
    gather_kernel<<<N / 256, 256>>>(logits);
    selectf_kernel<<<EXP, 256>>>(logits, N);
    assign_kernel<<<(int)(((size_t)N * 32 + 255) / 256), 256>>>(logits, out_w, out_i, N);
}

// round 10
// speedup vs baseline: 1.7571x; 1.1897x over previous
#include <cuda_runtime.h>
#include <cstdint>

#define HDIM 4096
#define EXP  64
#define BM   128
#define BK   32
#define NCH  (HDIM / BK)   // 128
#define GCAP 8192

typedef unsigned long long ull;

// ---------------------------------------------------------------------------
// Device globals
// ---------------------------------------------------------------------------
__device__ float    g_thresh[EXP];
__device__ unsigned g_hist0[EXP * 64];
__device__ unsigned g_b0[EXP];
__device__ unsigned g_remk[EXP];
__device__ int      g_cand_n[EXP];
__device__ unsigned g_cand[EXP][GCAP];
__device__ unsigned g_cand2[EXP][GCAP];

__device__ __forceinline__ unsigned sortable(float f) {
    unsigned u = __float_as_uint(f);
    return u ^ ((u & 0x80000000u) ? 0xFFFFFFFFu : 0x80000000u);
}
__device__ __forceinline__ uint32_t smem_u32(const void* p) {
    uint32_t a;
    asm("{ .reg .u64 t; cvta.to.shared.u64 t, %1; cvt.u32.u64 %0, t; }" : "=r"(a) : "l"(p));
    return a;
}
__device__ __forceinline__ void cp16(uint32_t dst, const void* src) {
    asm volatile("cp.async.cg.shared.global [%0], [%1], 16;" :: "r"(dst), "l"(src) : "memory");
}

// SMEM layout (dynamic):
//   xs[buf][row 0..127][k 0..31]  pitch 36 floats (144B)  -> 2*128*36 = 9216 floats
//   ws[buf][k 0..31][col 0..63]   pitch 64 floats         -> 2*32*64  = 4096 floats
#define XS_OFF(b) ((b) * 128 * 36)
#define WS_OFF(b) (9216 + (b) * 32 * 64)
#define GEMM_SMEM ((9216 + 4096) * 4)   // 53248 bytes

// ---------------------------------------------------------------------------
// Kernel 1: logits[N,64] = x[N,4096] @ W[4096,64], exact fp32.
// Per-output accumulation is a sequential k-ascending FFMA chain (one FFMA2
// lane each) — bit-identical to the R1 kernel that passed.
// cp.async staging: chunk c+1 streamed while chunk c computes.
// ---------------------------------------------------------------------------
__global__ __launch_bounds__(256, 3) void gemm_kernel(const float* __restrict__ x,
                                                      const float* __restrict__ W,
                                                      float* __restrict__ logits) {
    extern __shared__ float smem[];
    const int tid  = threadIdx.x;
    const int row0 = blockIdx.x * BM;
    const int rg   = tid >> 3;    // rows rg*4 .. +3
    const int cg   = tid & 7;     // cols cg*8 .. +7

    // copy-task maps
    const int xr   = tid >> 1;            // x: 2 segs per row... (u = tid + i*256)
    // per-thread copy tasks computed inline below

    ull acc[4][4];   // [row i][colpair p]; lanes = (col 8cg+2p, +1)
#pragma unroll
    for (int i = 0; i < 4; ++i)
#pragma unroll
        for (int p = 0; p < 4; ++p) acc[i][p] = 0ULL;
    (void)xr;

    // ---- stage helper: issue cp.asyncs for chunk c into buffer b ----
    auto stage = [&](int c, int b) {
        const int k0 = c * BK;
        // x tile: 128 rows x 32 floats = 1024 x 16B; 4 per thread
#pragma unroll
        for (int i = 0; i < 4; ++i) {
            int u = tid + i * 256;
            int r = u >> 3, seg = u & 7;
            uint32_t dst = smem_u32(&smem[XS_OFF(b) + r * 36 + seg * 4]);
            cp16(dst, x + (size_t)(row0 + r) * HDIM + k0 + seg * 4);
        }
        // W tile: 32 rows x 64 floats = 512 x 16B; 2 per thread
#pragma unroll
        for (int i = 0; i < 2; ++i) {
            int u = tid + i * 256;
            int wr = u >> 4, wseg = u & 15;
            uint32_t dst = smem_u32(&smem[WS_OFF(b) + wr * 64 + wseg * 4]);
            cp16(dst, W + (size_t)(k0 + wr) * EXP + wseg * 4);
        }
        asm volatile("cp.async.commit_group;" ::: "memory");
    };

    stage(0, 0);

    for (int c = 0; c < NCH; ++c) {
        const int buf = c & 1;
        if (c + 1 < NCH) {
            stage(c + 1, buf ^ 1);
            asm volatile("cp.async.wait_group 1;" ::: "memory");
        } else {
            asm volatile("cp.async.wait_group 0;" ::: "memory");
        }
        __syncthreads();

        const float* xb = &smem[XS_OFF(buf) + (rg * 4) * 36];
        const float* wb = &smem[WS_OFF(buf) + cg * 8];
#pragma unroll
        for (int g = 0; g < 8; ++g) {
            float4 av[4];
#pragma unroll
            for (int i = 0; i < 4; ++i)
                av[i] = *(const float4*)(xb + i * 36 + g * 4);
#pragma unroll
            for (int kk = 0; kk < 4; ++kk) {
                ull b2[4];
                {
                    const ull* bp = (const ull*)(wb + (g * 4 + kk) * 64);
                    ulonglong2 q0 = *(const ulonglong2*)(bp);
                    ulonglong2 q1 = *(const ulonglong2*)(bp + 2);
                    b2[0] = q0.x; b2[1] = q0.y; b2[2] = q1.x; b2[3] = q1.y;
                }
                float a0 = (kk == 0) ? av[0].x : (kk == 1) ? av[0].y : (kk == 2) ? av[0].z : av[0].w;
                float a1 = (kk == 0) ? av[1].x : (kk == 1) ? av[1].y : (kk == 2) ? av[1].z : av[1].w;
                float a2v = (kk == 0) ? av[2].x : (kk == 1) ? av[2].y : (kk == 2) ? av[2].z : av[2].w;
                float a3 = (kk == 0) ? av[3].x : (kk == 1) ? av[3].y : (kk == 2) ? av[3].z : av[3].w;
                ull a2[4];
                asm("mov.b64 %0, {%1, %1};" : "=l"(a2[0]) : "r"(__float_as_uint(a0)));
                asm("mov.b64 %0, {%1, %1};" : "=l"(a2[1]) : "r"(__float_as_uint(a1)));
                asm("mov.b64 %0, {%1, %1};" : "=l"(a2[2]) : "r"(__float_as_uint(a2v)));
                asm("mov.b64 %0, {%1, %1};" : "=l"(a2[3]) : "r"(__float_as_uint(a3)));
#pragma unroll
                for (int i = 0; i < 4; ++i)
#pragma unroll
                    for (int p = 0; p < 4; ++p)
                        asm("fma.rn.f32x2 %0, %1, %2, %0;"
                            : "+l"(acc[i][p]) : "l"(a2[i]), "l"(b2[p]));
            }
        }
        __syncthreads();
    }

    // writeback: 4 rows x 8 cols per thread
#pragma unroll
    for (int i = 0; i < 4; ++i) {
        float f[8];
#pragma unroll
        for (int p = 0; p < 4; ++p) {
            f[2 * p]     = __uint_as_float((unsigned)(acc[i][p] & 0xFFFFFFFFULL));
            f[2 * p + 1] = __uint_as_float((unsigned)(acc[i][p] >> 32));
        }
        float* dst = logits + (size_t)(row0 + rg * 4 + i) * EXP + cg * 8;
        *(float4*)dst       = make_float4(f[0], f[1], f[2], f[3]);
        *(float4*)(dst + 4) = make_float4(f[4], f[5], f[6], f[7]);
    }
}

// ---------------------------------------------------------------------------
// Kernel 2: fused row-major top-6-bit histograms for all 64 experts
// ---------------------------------------------------------------------------
__global__ __launch_bounds__(256) void hist0_kernel(const float* __restrict__ logits) {
    __shared__ unsigned h[EXP * 64];
    for (int i = threadIdx.x; i < EXP * 64; i += 256) h[i] = 0;
    __syncthreads();
    const int row0 = blockIdx.x * 128;
#pragma unroll
    for (int j = 0; j < 8; ++j) {
        int u = threadIdx.x + j * 256;
        int r = u >> 4, cgq = u & 15;
        float4 v = *(const float4*)(logits + (size_t)(row0 + r) * EXP + cgq * 4);
        float vv[4] = {v.x, v.y, v.z, v.w};
#pragma unroll
        for (int m = 0; m < 4; ++m)
            atomicAdd(&h[(cgq * 4 + m) * 64 + (sortable(vv[m]) >> 26)], 1u);
    }
    __syncthreads();
    for (int i = threadIdx.x; i < EXP * 64; i += 256) {
        unsigned c = h[i];
        if (c) atomicAdd(&g_hist0[i], c);
    }
}

// ---------------------------------------------------------------------------
// Kernel 3: pick top bucket + residual k per expert
// ---------------------------------------------------------------------------
__global__ void bucket_kernel(int k) {
    int e = threadIdx.x;   // 64 threads
    unsigned remk = (unsigned)k, cum = 0;
    int b = 63;
    for (; b > 0; --b) {
        unsigned h = g_hist0[e * 64 + b];
        if (cum + h >= remk) break;
        cum += h;
    }
    g_b0[e]   = (unsigned)b;
    g_remk[e] = remk - cum;
}

// ---------------------------------------------------------------------------
// Kernel 4: row-major gather of bucket candidates into per-expert lists
// ---------------------------------------------------------------------------
__global__ __launch_bounds__(128) void gather_kernel(const float* __restrict__ logits) {
    __shared__ unsigned sb0[EXP];
    if (threadIdx.x < EXP) sb0[threadIdx.x] = g_b0[threadIdx.x];
    __syncthreads();
    const int t = blockIdx.x * 128 + threadIdx.x;   // token row
    const float4* row = (const float4*)(logits + (size_t)t * EXP);
#pragma unroll
    for (int q = 0; q < 16; ++q) {
        float4 v = row[q];
        float vv[4] = {v.x, v.y, v.z, v.w};
#pragma unroll
        for (int m = 0; m < 4; ++m) {
            int e = q * 4 + m;
            unsigned u = sortable(vv[m]);
            if ((u >> 26) == sb0[e]) {
                int i = atomicAdd(&g_cand_n[e], 1);
                if (i < GCAP) g_cand[e][i] = u;
            }
        }
    }
}

// ---------------------------------------------------------------------------
// Kernel 5: per-expert k-th largest. Local radix on gathered candidates;
// full-column scanning fallback if the bucket overflowed GCAP.
// ---------------------------------------------------------------------------
__global__ __launch_bounds__(256) void selectf_kernel(const float* __restrict__ logits,
                                                      int N) {
    __shared__ unsigned hist[256];
    __shared__ unsigned s_bv, s_remk, s_prefix, s_n2;
    const int e   = blockIdx.x;
    const int tid = threadIdx.x;
    const unsigned b0 = g_b0[e];
    const int cn = g_cand_n[e];
    const int SH[4] = {18, 10, 2, 0};
    const unsigned MK[4] = {255, 255, 255, 3};

    if (tid == 0) { s_remk = g_remk[e]; s_prefix = 0; }
    __syncthreads();

    if (cn <= GCAP) {
        unsigned* cur = g_cand[e];
        unsigned* alt = g_cand2[e];
        int n = cn;
        for (int p = 0; p < 4; ++p) {
            const int sh = SH[p]; const unsigned mk = MK[p];
            hist[tid] = 0;
            __syncthreads();
            for (int j = tid; j < n; j += 256) atomicAdd(&hist[(cur[j] >> sh) & mk], 1u);
            __syncthreads();
            if (tid == 0) {
                unsigned remk = s_remk, cum = 0;
                int b = (int)mk;
                for (; b > 0; --b) { unsigned h = hist[b]; if (cum + h >= remk) break; cum += h; }
                s_bv = (unsigned)b; s_remk = remk - cum;
                s_prefix |= ((unsigned)b) << sh; s_n2 = 0;
            }
            __syncthreads();
            if (p < 3) {
                unsigned bv = s_bv;
                for (int j = tid; j < n; j += 256) {
                    unsigned key = cur[j];
                    if (((key >> sh) & mk) == bv) { unsigned q = atomicAdd(&s_n2, 1u); alt[q] = key; }
                }
                __syncthreads();
                n = (int)s_n2;
                unsigned* tmp = cur; cur = alt; alt = tmp;
            }
        }
        if (tid == 0) {
            unsigned key = (b0 << 26) | s_prefix;
            unsigned bits = (key & 0x80000000u) ? (key ^ 0x80000000u) : ~key;
            g_thresh[e] = __uint_as_float(bits);
        }
    } else {
        unsigned pmask = 0xFC000000u;
        if (tid == 0) s_prefix = b0 << 26;
        __syncthreads();
        for (int p = 0; p < 4; ++p) {
            const int sh = SH[p]; const unsigned mk = MK[p];
            hist[tid] = 0;
            __syncthreads();
            const unsigned pre = s_prefix;
            for (int i = tid; i < N; i += 256) {
                unsigned u = sortable(logits[(size_t)i * EXP + e]);
                if ((u & pmask) == pre) atomicAdd(&hist[(u >> sh) & mk], 1u);
            }
            __syncthreads();
            if (tid == 0) {
                unsigned remk = s_remk, cum = 0;
                int b = (int)mk;
                for (; b > 0; --b) { unsigned h = hist[b]; if (cum + h >= remk) break; cum += h; }
                s_prefix = pre | (((unsigned)b) << sh); s_remk = remk - cum;
            }
            pmask |= mk << sh;
            __syncthreads();
        }
        if (tid == 0) {
            unsigned key = s_prefix;
            unsigned bits = (key & 0x80000000u) ? (key ^ 0x80000000u) : ~key;
            g_thresh[e] = __uint_as_float(bits);
        }
    }
}

// ---------------------------------------------------------------------------
// Kernel 6: conflict resolution + fallback argmax. One warp per token.
// ---------------------------------------------------------------------------
__global__ __launch_bounds__(256) void assign_kernel(const float* __restrict__ logits,
                                                     float* __restrict__ out_w,
                                                     float* __restrict__ out_i,
                                                     int N) {
    const int gwarp = (int)((blockIdx.x * (size_t)blockDim.x + threadIdx.x) >> 5);
    const int lane  = threadIdx.x & 31;
    if (gwarp >= N) return;

    const float NEG_INF = __int_as_float(0xff800000);
    float2 v = *(const float2*)(logits + (size_t)gwarp * EXP + lane * 2);
    float t0 = g_thresh[lane * 2];
    float t1 = g_thresh[lane * 2 + 1];

    float cs = NEG_INF; int ci = 127;                  // claimed best
    if (v.x >= t0)             { cs = v.x; ci = lane * 2; }
    if (v.y >= t1 && v.y > cs) { cs = v.y; ci = lane * 2 + 1; }

    float fs = v.x; int fi = lane * 2;                 // fallback argmax
    if (v.y > fs) { fs = v.y; fi = lane * 2 + 1; }

#pragma unroll
    for (int off = 16; off; off >>= 1) {
        float os = __shfl_xor_sync(0xFFFFFFFFu, cs, off);
        int   oi = __shfl_xor_sync(0xFFFFFFFFu, ci, off);
        if (os > cs || (os == cs && oi < ci)) { cs = os; ci = oi; }
        float ofs = __shfl_xor_sync(0xFFFFFFFFu, fs, off);
        int   ofi = __shfl_xor_sync(0xFFFFFFFFu, fi, off);
        if (ofs > fs || (ofs == fs && ofi < fi)) { fs = ofs; fi = ofi; }
    }

    if (lane == 0) {
        float w; int e;
        if (ci < EXP) { w = cs; e = ci; }
        else          { w = fs; e = fi; }
        out_w[gwarp] = w;
        out_i[gwarp] = (float)e;
    }
}

// ---------------------------------------------------------------------------
// Output layout: [0,N) weights | [N,2N) indices (float) | [2N, 2N+N*E) logits
// ---------------------------------------------------------------------------
extern "C" void kernel_launch(void* const* d_in, const int* in_sizes, int n_in,
                              void* d_out, int out_size) {
    const float* x = (const float*)d_in[0];
    const float* W = (const float*)d_in[1];
    const int N = in_sizes[0] / HDIM;   // 32768

    float* out    = (float*)d_out;
    float* out_w  = out;
    float* out_i  = out + N;
    float* logits = out + 2 * (size_t)N;

    int k = N / EXP;
    if (k < 1) k = 1;
    if (k > N) k = N;

    static int smem_set = 0;
    if (!smem_set) {
        cudaFuncSetAttribute(gemm_kernel, cudaFuncAttributeMaxDynamicSharedMemorySize, GEMM_SMEM);
        smem_set = 1;
    }

    void* p;
    cudaGetSymbolAddress(&p, g_hist0);  cudaMemsetAsync(p, 0, EXP * 64 * sizeof(unsigned));
    cudaGetSymbolAddress(&p, g_cand_n); cudaMemsetAsync(p, 0, EXP * sizeof(int));

    gemm_kernel<<<N / BM, 256, GEMM_SMEM>>>(x, W, logits);
    hist0_kernel<<<N / 128, 256>>>(logits);
    bucket_kernel<<<1, 64>>>(k);
    gather_kernel<<<N / 128, 128>>>(logits);
    selectf_kernel<<<EXP, 256>>>(logits, N);
    assign_kernel<<<(int)(((size_t)N * 32 + 255) / 256), 256>>>(logits, out_w, out_i, N);
}